// round 1
// baseline (speedup 1.0000x reference)
#include <cuda_runtime.h>
#include <cstdint>

// Problem constants (fixed by reference)
#define NN   100000
#define EE   1600000
#define FH   128      // F_IN == H == HG
#define H3   384      // 3*HG
#define CC   40
#define LL   3

// ---------------- scratch (device globals; no allocation allowed) ----------
__device__ float g_xh[(size_t)NN * FH];
__device__ float g_xw[(size_t)NN * FH];
__device__ float g_h [(size_t)NN * FH];
__device__ float g_gi[(size_t)NN * H3];
__device__ float g_gh[(size_t)NN * H3];
__device__ float g_deg [NN];
__device__ float g_dinv[NN];

// ---------------- degree / normalization ----------------
__global__ void init_deg_kernel() {
    int i = blockIdx.x * blockDim.x + threadIdx.x;
    if (i < NN) g_deg[i] = 1.0f;   // self-loop weight 1
}

__global__ void accum_deg_kernel(const int* __restrict__ dst,
                                 const float* __restrict__ ew) {
    int e = blockIdx.x * blockDim.x + threadIdx.x;
    if (e < EE) atomicAdd(&g_deg[dst[e]], ew[e]);
}

__global__ void dinv_kernel() {
    int i = blockIdx.x * blockDim.x + threadIdx.x;
    if (i < NN) g_dinv[i] = rsqrtf(g_deg[i]);   // deg >= 1 always
}

// ---------------- GEMM: C[M,Ncols] = A[M,128] * B (+bias)(+relu) ----------
// TRANSB=false: B is [128, Ncols] row-major
// TRANSB=true : B is [Ncols, 128] row-major (C = A * B^T)
template<bool TRANSB, bool BIAS, bool RELU>
__global__ void gemm_kernel(const float* __restrict__ A,
                            const float* __restrict__ B,
                            const float* __restrict__ bias,
                            float* __restrict__ C,
                            int M, int Ncols) {
    constexpr int K  = 128;
    constexpr int BM = 64, BN = 64, BK = 16;
    __shared__ float As[BK][BM + 4];
    __shared__ float Bs[BK][BN + 4];

    const int tid = threadIdx.x;              // 256 threads
    const int bm = blockIdx.y * BM;
    const int bn = blockIdx.x * BN;
    const int tx = tid & 15;                  // 0..15 -> 4 cols each
    const int ty = tid >> 4;                  // 0..15 -> 4 rows each

    float acc[4][4] = {};

    for (int k0 = 0; k0 < K; k0 += BK) {
        // ---- load A tile (64x16), transposed into As[k][m]
        {
            const int arow = tid >> 2;            // 0..63
            const int acol = (tid & 3) << 2;      // 0,4,8,12
            float4 av = make_float4(0.f, 0.f, 0.f, 0.f);
            const int gr = bm + arow;
            if (gr < M)
                av = *(const float4*)(A + (size_t)gr * K + k0 + acol);
            As[acol + 0][arow] = av.x;
            As[acol + 1][arow] = av.y;
            As[acol + 2][arow] = av.z;
            As[acol + 3][arow] = av.w;
        }
        // ---- load B tile into Bs[k][n]
        if (!TRANSB) {
            const int brow = tid >> 4;            // 0..15 (k)
            const int bcol = (tid & 15) << 2;     // 0..60 (n)
            const int gc = bn + bcol;
            float4 bv = make_float4(0.f, 0.f, 0.f, 0.f);
            if (gc + 3 < Ncols) {
                bv = *(const float4*)(B + (size_t)(k0 + brow) * Ncols + gc);
            } else {
                float t0 = (gc + 0 < Ncols) ? B[(size_t)(k0 + brow) * Ncols + gc + 0] : 0.f;
                float t1 = (gc + 1 < Ncols) ? B[(size_t)(k0 + brow) * Ncols + gc + 1] : 0.f;
                float t2 = (gc + 2 < Ncols) ? B[(size_t)(k0 + brow) * Ncols + gc + 2] : 0.f;
                float t3 = (gc + 3 < Ncols) ? B[(size_t)(k0 + brow) * Ncols + gc + 3] : 0.f;
                bv = make_float4(t0, t1, t2, t3);
            }
            Bs[brow][bcol + 0] = bv.x;
            Bs[brow][bcol + 1] = bv.y;
            Bs[brow][bcol + 2] = bv.z;
            Bs[brow][bcol + 3] = bv.w;
        } else {
            const int nrow = tid >> 2;            // 0..63 (n)
            const int kcol = (tid & 3) << 2;      // 0,4,8,12 (k)
            // TRANSB path only used with Ncols multiple of 64 -> no guard needed
            float4 bv = *(const float4*)(B + (size_t)(bn + nrow) * K + k0 + kcol);
            Bs[kcol + 0][nrow] = bv.x;
            Bs[kcol + 1][nrow] = bv.y;
            Bs[kcol + 2][nrow] = bv.z;
            Bs[kcol + 3][nrow] = bv.w;
        }
        __syncthreads();

        #pragma unroll
        for (int k = 0; k < BK; k++) {
            float4 a = *(const float4*)(&As[k][ty << 2]);
            float4 b = *(const float4*)(&Bs[k][tx << 2]);
            acc[0][0] += a.x * b.x; acc[0][1] += a.x * b.y;
            acc[0][2] += a.x * b.z; acc[0][3] += a.x * b.w;
            acc[1][0] += a.y * b.x; acc[1][1] += a.y * b.y;
            acc[1][2] += a.y * b.z; acc[1][3] += a.y * b.w;
            acc[2][0] += a.z * b.x; acc[2][1] += a.z * b.y;
            acc[2][2] += a.z * b.z; acc[2][3] += a.z * b.w;
            acc[3][0] += a.w * b.x; acc[3][1] += a.w * b.y;
            acc[3][2] += a.w * b.z; acc[3][3] += a.w * b.w;
        }
        __syncthreads();
    }

    float bv[4] = {0.f, 0.f, 0.f, 0.f};
    if (BIAS) {
        #pragma unroll
        for (int j = 0; j < 4; j++) {
            int c = bn + (tx << 2) + j;
            bv[j] = (c < Ncols) ? bias[c] : 0.f;
        }
    }
    #pragma unroll
    for (int i = 0; i < 4; i++) {
        int r = bm + (ty << 2) + i;
        if (r >= M) continue;
        #pragma unroll
        for (int j = 0; j < 4; j++) {
            int c = bn + (tx << 2) + j;
            if (c >= Ncols) continue;
            float v = acc[i][j];
            if (BIAS) v += bv[j];
            if (RELU) v = fmaxf(v, 0.f);
            C[(size_t)r * Ncols + c] = v;
        }
    }
}

// ---------------- self-loop init: agg = xw * dinv^2 ----------------
__global__ void selfloop_kernel(const float* __restrict__ xw,
                                float* __restrict__ agg) {
    size_t idx = (size_t)blockIdx.x * blockDim.x + threadIdx.x;
    if (idx >= (size_t)NN * FH) return;
    int n = (int)(idx >> 7);
    float di = g_dinv[n];
    agg[idx] = xw[idx] * di * di;
}

// ---------------- edge scatter: one warp per edge ----------------
__global__ void scatter_kernel(const int* __restrict__ src,
                               const int* __restrict__ dst,
                               const float* __restrict__ ew,
                               const float* __restrict__ xw,
                               float* __restrict__ agg) {
    int warp = (blockIdx.x * blockDim.x + threadIdx.x) >> 5;
    int lane = threadIdx.x & 31;
    if (warp >= EE) return;
    int s = src[warp];
    int d = dst[warp];
    float norm = g_dinv[s] * ew[warp] * g_dinv[d];
    float4 v = ((const float4*)(xw + (size_t)s * FH))[lane];
    float* base = agg + (size_t)d * FH + (lane << 2);
    atomicAdd(base + 0, v.x * norm);
    atomicAdd(base + 1, v.y * norm);
    atomicAdd(base + 2, v.z * norm);
    atomicAdd(base + 3, v.w * norm);
}

// ---------------- bias + relu (in place) ----------------
__global__ void bias_relu_kernel(float* __restrict__ xh,
                                 const float* __restrict__ b) {
    size_t idx = (size_t)blockIdx.x * blockDim.x + threadIdx.x;
    if (idx >= (size_t)NN * FH) return;
    int f = (int)(idx & (FH - 1));
    xh[idx] = fmaxf(xh[idx] + b[f], 0.f);
}

// ---------------- GRU elementwise ----------------
__global__ void gru_kernel(const float* __restrict__ gi,
                           const float* __restrict__ gh,
                           const float* __restrict__ hprev,
                           float* __restrict__ hout) {
    size_t idx = (size_t)blockIdx.x * blockDim.x + threadIdx.x;
    if (idx >= (size_t)NN * FH) return;
    int n = (int)(idx >> 7);
    int j = (int)(idx & (FH - 1));
    size_t base = (size_t)n * H3 + j;
    float ir = gi[base          ];
    float iz = gi[base + FH     ];
    float in_ = gi[base + 2 * FH];
    float hr = gh[base          ];
    float hz = gh[base + FH     ];
    float hn = gh[base + 2 * FH];
    float hv = hprev[idx];
    float r = 1.f / (1.f + expf(-(ir + hr)));
    float z = 1.f / (1.f + expf(-(iz + hz)));
    float nn = tanhf(in_ + r * hn);
    hout[idx] = (1.f - z) * nn + z * hv;
}

// ---------------- host orchestration ----------------
static void run_gemm(const float* A, const float* B, const float* bias,
                     float* C, int M, int Ncols, bool transB, bool hasBias,
                     bool relu) {
    dim3 grid((Ncols + 63) / 64, (M + 63) / 64);
    dim3 blk(256);
    if (transB) {
        if (hasBias) gemm_kernel<true, true, false><<<grid, blk>>>(A, B, bias, C, M, Ncols);
        else         gemm_kernel<true, false, false><<<grid, blk>>>(A, B, bias, C, M, Ncols);
    } else {
        if (hasBias && relu)      gemm_kernel<false, true, true ><<<grid, blk>>>(A, B, bias, C, M, Ncols);
        else if (hasBias)         gemm_kernel<false, true, false><<<grid, blk>>>(A, B, bias, C, M, Ncols);
        else                      gemm_kernel<false, false, false><<<grid, blk>>>(A, B, bias, C, M, Ncols);
    }
}

extern "C" void kernel_launch(void* const* d_in, const int* in_sizes, int n_in,
                              void* d_out, int out_size) {
    const float* x     = (const float*)d_in[0];
    const int*   ei    = (const int*)  d_in[1];
    const float* ew    = (const float*)d_in[2];
    const float* h0    = (const float*)d_in[3];
    const float* linW  = (const float*)d_in[4];
    const float* linB  = (const float*)d_in[5];
    const float* convW = (const float*)d_in[6];
    const float* convB = (const float*)d_in[7];
    const float* Wih   = (const float*)d_in[8];
    const float* Whh   = (const float*)d_in[9];
    const float* bih   = (const float*)d_in[10];
    const float* bhh   = (const float*)d_in[11];
    const float* fcW   = (const float*)d_in[12];
    const float* fcB   = (const float*)d_in[13];
    float* out = (float*)d_out;

    const int* src = ei;
    const int* dst = ei + EE;

    // scratch symbol addresses (not stream ops; graph-capture safe)
    float *p_xh, *p_xw, *p_h, *p_gi, *p_gh;
    cudaGetSymbolAddress((void**)&p_xh, g_xh);
    cudaGetSymbolAddress((void**)&p_xw, g_xw);
    cudaGetSymbolAddress((void**)&p_h,  g_h);
    cudaGetSymbolAddress((void**)&p_gi, g_gi);
    cudaGetSymbolAddress((void**)&p_gh, g_gh);

    const size_t NF = (size_t)NN * FH;
    const int EB = 256;

    // degree + normalization
    init_deg_kernel<<<(NN + 255) / 256, 256>>>();
    accum_deg_kernel<<<(EE + EB - 1) / EB, EB>>>(dst, ew);
    dinv_kernel<<<(NN + 255) / 256, 256>>>();

    // xh = relu(x @ linW + linB)
    run_gemm(x, linW, linB, p_xh, NN, FH, false, true, true);

    // h = GRU(xh, h0)
    run_gemm(p_xh, Wih, bih, p_gi, NN, H3, true, true, false);
    run_gemm(h0,   Whh, bhh, p_gh, NN, H3, true, true, false);
    gru_kernel<<<(int)((NF + 255) / 256), 256>>>(p_gi, p_gh, h0, p_h);

    for (int l = 0; l < LL; l++) {
        const float* W = convW + (size_t)l * FH * FH;
        const float* b = convB + (size_t)l * FH;
        // xw = xh @ W
        run_gemm(p_xh, W, nullptr, p_xw, NN, FH, false, false, false);
        // agg (into xh, overwriting): self-loop + edge scatter
        selfloop_kernel<<<(int)((NF + 255) / 256), 256>>>(p_xw, p_xh);
        scatter_kernel<<<(EE * 32 + 255) / 256, 256>>>(src, dst, ew, p_xw, p_xh);
        // xh = relu(agg + b)
        bias_relu_kernel<<<(int)((NF + 255) / 256), 256>>>(p_xh, b);
        // h = GRU(xh, h)
        run_gemm(p_xh, Wih, bih, p_gi, NN, H3, true, true, false);
        run_gemm(p_h,  Whh, bhh, p_gh, NN, H3, true, true, false);
        gru_kernel<<<(int)((NF + 255) / 256), 256>>>(p_gi, p_gh, p_h, p_h);
    }

    // out = h @ fcW + fcB
    run_gemm(p_h, fcW, fcB, out, NN, CC, false, true, false);
}

// round 3
// speedup vs baseline: 1.5573x; 1.5573x over previous
#include <cuda_runtime.h>
#include <cstdint>

// Problem constants (fixed by reference)
#define NN   100000
#define EE   1600000
#define FH   128      // F_IN == H == HG
#define H3   384      // 3*HG
#define CC   40
#define LL   3

// ---------------- scratch (device globals; no allocation allowed) ----------
__device__ float g_xh[(size_t)NN * FH];
__device__ float g_xw[(size_t)NN * FH];
__device__ float g_h [(size_t)NN * FH];
__device__ float g_gi[(size_t)NN * H3];
__device__ float g_gh[(size_t)NN * H3];
__device__ float g_deg [NN];
__device__ float g_dinv[NN];

// ---------------- degree / normalization ----------------
__global__ void init_deg_kernel() {
    int i = blockIdx.x * blockDim.x + threadIdx.x;
    if (i < NN) g_deg[i] = 1.0f;   // self-loop weight 1
}

__global__ void accum_deg_kernel(const int* __restrict__ dst,
                                 const float* __restrict__ ew) {
    int e = blockIdx.x * blockDim.x + threadIdx.x;
    if (e < EE) atomicAdd(&g_deg[dst[e]], ew[e]);
}

__global__ void dinv_kernel() {
    int i = blockIdx.x * blockDim.x + threadIdx.x;
    if (i < NN) g_dinv[i] = rsqrtf(g_deg[i]);   // deg >= 1 always
}

// =====================================================================
// TF32 tensor-core GEMM: C[M,Ncols] = A[M,128] * B (+bias)(+relu)
//   TRANSB=false: B is [128, Ncols] row-major
//   TRANSB=true : B is [Ncols, 128] row-major (C = A * B^T)
// Requires Ncols % 128 == 0. CTA tile 128x128, full K=128 in smem.
// 8 warps, warp tile 64x32, mma.sync.m16n8k8.tf32.
// =====================================================================
#define TS 132   // smem row stride (floats); bank-conflict-free pad
#define GEMM_SMEM_BYTES (2 * 128 * TS * 4)

__device__ __forceinline__ float to_tf32(float v) {
    uint32_t o;
    asm volatile("cvt.rna.tf32.f32 %0, %1;" : "=r"(o) : "f"(v));
    return __uint_as_float(o);
}

__device__ __forceinline__ void mma_tf32(float* d, const uint32_t* a,
                                         const uint32_t* b) {
    asm volatile(
        "mma.sync.aligned.m16n8k8.row.col.f32.tf32.tf32.f32 "
        "{%0,%1,%2,%3}, {%4,%5,%6,%7}, {%8,%9}, {%0,%1,%2,%3};\n"
        : "+f"(d[0]), "+f"(d[1]), "+f"(d[2]), "+f"(d[3])
        : "r"(a[0]), "r"(a[1]), "r"(a[2]), "r"(a[3]),
          "r"(b[0]), "r"(b[1]));
}

template<bool TRANSB, bool BIAS, bool RELU>
__global__ __launch_bounds__(256, 1)
void gemm_tf32_kernel(const float* __restrict__ A,
                      const float* __restrict__ B,
                      const float* __restrict__ bias,
                      float* __restrict__ C,
                      int M, int Ncols) {
    extern __shared__ float smem[];
    float* As = smem;              // [128][TS]  (m-major: As[m][k])
    float* Bs = smem + 128 * TS;   // [128][TS]  (n-major: Bs[n][k])

    const int tid  = threadIdx.x;
    const int lane = tid & 31;
    const int warp = tid >> 5;
    const int bm = blockIdx.y * 128;
    const int bn = blockIdx.x * 128;

    // ---- fill As[m][k] = tf32(A[bm+m][k]) ----
    #pragma unroll
    for (int it = 0; it < 16; it++) {
        int i = it * 256 + tid;         // 4096 float4 slots
        int m = i >> 5;
        int kq = (i & 31) << 2;
        int gr = bm + m;
        float4 v = make_float4(0.f, 0.f, 0.f, 0.f);
        if (gr < M) v = *(const float4*)(A + (size_t)gr * 128 + kq);
        float4 w = make_float4(to_tf32(v.x), to_tf32(v.y),
                               to_tf32(v.z), to_tf32(v.w));
        *(float4*)(As + m * TS + kq) = w;
    }
    // ---- fill Bs[n][k] ----
    if (TRANSB) {
        // B row-major [Ncols,128]: Bs[n][k] = B[bn+n][k]  (coalesced)
        #pragma unroll
        for (int it = 0; it < 16; it++) {
            int i = it * 256 + tid;
            int n = i >> 5;
            int kq = (i & 31) << 2;
            float4 v = *(const float4*)(B + (size_t)(bn + n) * 128 + kq);
            float4 w = make_float4(to_tf32(v.x), to_tf32(v.y),
                                   to_tf32(v.z), to_tf32(v.w));
            *(float4*)(Bs + n * TS + kq) = w;
        }
    } else {
        // B row-major [128,Ncols]: Bs[n][k] = B[k][bn+n] (transpose fill)
        #pragma unroll
        for (int it = 0; it < 16; it++) {
            int i = it * 256 + tid;
            int k = i >> 5;
            int nq = (i & 31) << 2;
            float4 v = *(const float4*)(B + (size_t)k * Ncols + bn + nq);
            Bs[(nq + 0) * TS + k] = to_tf32(v.x);
            Bs[(nq + 1) * TS + k] = to_tf32(v.y);
            Bs[(nq + 2) * TS + k] = to_tf32(v.z);
            Bs[(nq + 3) * TS + k] = to_tf32(v.w);
        }
    }
    __syncthreads();

    // warp tile: 64 rows x 32 cols
    const int wm = (warp & 1) * 64;   // 0 or 64
    const int wn = (warp >> 1) * 32;  // 0,32,64,96
    const int lr = lane >> 2;         // 0..7
    const int lc = lane & 3;          // 0..3

    float acc[4][4][4];
    #pragma unroll
    for (int mi = 0; mi < 4; mi++)
        #pragma unroll
        for (int ni = 0; ni < 4; ni++)
            #pragma unroll
            for (int j = 0; j < 4; j++) acc[mi][ni][j] = 0.f;

    #pragma unroll
    for (int k0 = 0; k0 < 128; k0 += 8) {
        uint32_t af[4][4], bf[4][2];
        #pragma unroll
        for (int mi = 0; mi < 4; mi++) {
            const float* p = As + (wm + mi * 16 + lr) * TS + k0 + lc;
            af[mi][0] = __float_as_uint(p[0]);
            af[mi][1] = __float_as_uint(p[8 * TS]);
            af[mi][2] = __float_as_uint(p[4]);
            af[mi][3] = __float_as_uint(p[8 * TS + 4]);
        }
        #pragma unroll
        for (int ni = 0; ni < 4; ni++) {
            const float* p = Bs + (wn + ni * 8 + lr) * TS + k0 + lc;
            bf[ni][0] = __float_as_uint(p[0]);
            bf[ni][1] = __float_as_uint(p[4]);
        }
        #pragma unroll
        for (int mi = 0; mi < 4; mi++)
            #pragma unroll
            for (int ni = 0; ni < 4; ni++)
                mma_tf32(acc[mi][ni], af[mi], bf[ni]);
    }

    // ---- epilogue ----
    #pragma unroll
    for (int mi = 0; mi < 4; mi++) {
        int r0 = bm + wm + mi * 16 + lr;
        int r1 = r0 + 8;
        #pragma unroll
        for (int ni = 0; ni < 4; ni++) {
            int c0 = bn + wn + ni * 8 + (lc << 1);
            float b0 = 0.f, b1 = 0.f;
            if (BIAS) { b0 = bias[c0]; b1 = bias[c0 + 1]; }
            float v0 = acc[mi][ni][0] + b0;
            float v1 = acc[mi][ni][1] + b1;
            float v2 = acc[mi][ni][2] + b0;
            float v3 = acc[mi][ni][3] + b1;
            if (RELU) {
                v0 = fmaxf(v0, 0.f); v1 = fmaxf(v1, 0.f);
                v2 = fmaxf(v2, 0.f); v3 = fmaxf(v3, 0.f);
            }
            if (r0 < M) *(float2*)(C + (size_t)r0 * Ncols + c0) = make_float2(v0, v1);
            if (r1 < M) *(float2*)(C + (size_t)r1 * Ncols + c0) = make_float2(v2, v3);
        }
    }
}

// ---------------- fp32 fallback GEMM (used for fc, Ncols=40) --------------
template<bool TRANSB, bool BIAS, bool RELU>
__global__ void gemm_kernel(const float* __restrict__ A,
                            const float* __restrict__ B,
                            const float* __restrict__ bias,
                            float* __restrict__ C,
                            int M, int Ncols) {
    constexpr int K  = 128;
    constexpr int BM = 64, BN = 64, BK = 16;
    __shared__ float As[BK][BM + 4];
    __shared__ float Bs[BK][BN + 4];

    const int tid = threadIdx.x;
    const int bm = blockIdx.y * BM;
    const int bn = blockIdx.x * BN;
    const int tx = tid & 15;
    const int ty = tid >> 4;

    float acc[4][4] = {};

    for (int k0 = 0; k0 < K; k0 += BK) {
        {
            const int arow = tid >> 2;
            const int acol = (tid & 3) << 2;
            float4 av = make_float4(0.f, 0.f, 0.f, 0.f);
            const int gr = bm + arow;
            if (gr < M)
                av = *(const float4*)(A + (size_t)gr * K + k0 + acol);
            As[acol + 0][arow] = av.x;
            As[acol + 1][arow] = av.y;
            As[acol + 2][arow] = av.z;
            As[acol + 3][arow] = av.w;
        }
        if (!TRANSB) {
            const int brow = tid >> 4;
            const int bcol = (tid & 15) << 2;
            const int gc = bn + bcol;
            float t0 = (gc + 0 < Ncols) ? B[(size_t)(k0 + brow) * Ncols + gc + 0] : 0.f;
            float t1 = (gc + 1 < Ncols) ? B[(size_t)(k0 + brow) * Ncols + gc + 1] : 0.f;
            float t2 = (gc + 2 < Ncols) ? B[(size_t)(k0 + brow) * Ncols + gc + 2] : 0.f;
            float t3 = (gc + 3 < Ncols) ? B[(size_t)(k0 + brow) * Ncols + gc + 3] : 0.f;
            Bs[brow][bcol + 0] = t0;
            Bs[brow][bcol + 1] = t1;
            Bs[brow][bcol + 2] = t2;
            Bs[brow][bcol + 3] = t3;
        } else {
            const int nrow = tid >> 2;
            const int kcol = (tid & 3) << 2;
            float4 bv = *(const float4*)(B + (size_t)(bn + nrow) * K + k0 + kcol);
            Bs[kcol + 0][nrow] = bv.x;
            Bs[kcol + 1][nrow] = bv.y;
            Bs[kcol + 2][nrow] = bv.z;
            Bs[kcol + 3][nrow] = bv.w;
        }
        __syncthreads();

        #pragma unroll
        for (int k = 0; k < BK; k++) {
            float4 a = *(const float4*)(&As[k][ty << 2]);
            float4 b = *(const float4*)(&Bs[k][tx << 2]);
            acc[0][0] += a.x * b.x; acc[0][1] += a.x * b.y;
            acc[0][2] += a.x * b.z; acc[0][3] += a.x * b.w;
            acc[1][0] += a.y * b.x; acc[1][1] += a.y * b.y;
            acc[1][2] += a.y * b.z; acc[1][3] += a.y * b.w;
            acc[2][0] += a.z * b.x; acc[2][1] += a.z * b.y;
            acc[2][2] += a.z * b.z; acc[2][3] += a.z * b.w;
            acc[3][0] += a.w * b.x; acc[3][1] += a.w * b.y;
            acc[3][2] += a.w * b.z; acc[3][3] += a.w * b.w;
        }
        __syncthreads();
    }

    float bv[4] = {0.f, 0.f, 0.f, 0.f};
    if (BIAS) {
        #pragma unroll
        for (int j = 0; j < 4; j++) {
            int c = bn + (tx << 2) + j;
            bv[j] = (c < Ncols) ? bias[c] : 0.f;
        }
    }
    #pragma unroll
    for (int i = 0; i < 4; i++) {
        int r = bm + (ty << 2) + i;
        if (r >= M) continue;
        #pragma unroll
        for (int j = 0; j < 4; j++) {
            int c = bn + (tx << 2) + j;
            if (c >= Ncols) continue;
            float v = acc[i][j];
            if (BIAS) v += bv[j];
            if (RELU) v = fmaxf(v, 0.f);
            C[(size_t)r * Ncols + c] = v;
        }
    }
}

// ---------------- self-loop init: agg = xw * dinv^2 ----------------
__global__ void selfloop_kernel(const float* __restrict__ xw,
                                float* __restrict__ agg) {
    size_t idx = (size_t)blockIdx.x * blockDim.x + threadIdx.x;
    if (idx >= (size_t)NN * FH) return;
    int n = (int)(idx >> 7);
    float di = g_dinv[n];
    agg[idx] = xw[idx] * di * di;
}

// ---------------- edge scatter: one warp per edge ----------------
__global__ void scatter_kernel(const int* __restrict__ src,
                               const int* __restrict__ dst,
                               const float* __restrict__ ew,
                               const float* __restrict__ xw,
                               float* __restrict__ agg) {
    int warp = (blockIdx.x * blockDim.x + threadIdx.x) >> 5;
    int lane = threadIdx.x & 31;
    if (warp >= EE) return;
    int s = src[warp];
    int d = dst[warp];
    float norm = g_dinv[s] * ew[warp] * g_dinv[d];
    float4 v = ((const float4*)(xw + (size_t)s * FH))[lane];
    float* base = agg + (size_t)d * FH + (lane << 2);
    atomicAdd(base + 0, v.x * norm);
    atomicAdd(base + 1, v.y * norm);
    atomicAdd(base + 2, v.z * norm);
    atomicAdd(base + 3, v.w * norm);
}

// ---------------- bias + relu (in place) ----------------
__global__ void bias_relu_kernel(float* __restrict__ xh,
                                 const float* __restrict__ b) {
    size_t idx = (size_t)blockIdx.x * blockDim.x + threadIdx.x;
    if (idx >= (size_t)NN * FH) return;
    int f = (int)(idx & (FH - 1));
    xh[idx] = fmaxf(xh[idx] + b[f], 0.f);
}

// ---------------- GRU elementwise ----------------
__global__ void gru_kernel(const float* __restrict__ gi,
                           const float* __restrict__ gh,
                           const float* __restrict__ hprev,
                           float* __restrict__ hout) {
    size_t idx = (size_t)blockIdx.x * blockDim.x + threadIdx.x;
    if (idx >= (size_t)NN * FH) return;
    int n = (int)(idx >> 7);
    int j = (int)(idx & (FH - 1));
    size_t base = (size_t)n * H3 + j;
    float ir = gi[base          ];
    float iz = gi[base + FH     ];
    float in_ = gi[base + 2 * FH];
    float hr = gh[base          ];
    float hz = gh[base + FH     ];
    float hn = gh[base + 2 * FH];
    float hv = hprev[idx];
    float r = 1.f / (1.f + expf(-(ir + hr)));
    float z = 1.f / (1.f + expf(-(iz + hz)));
    float nn = tanhf(in_ + r * hn);
    hout[idx] = (1.f - z) * nn + z * hv;
}

// ---------------- host orchestration ----------------
static void run_gemm_tf32(const float* A, const float* B, const float* bias,
                          float* C, int M, int Ncols, bool transB,
                          bool hasBias, bool relu) {
    dim3 grid(Ncols / 128, (M + 127) / 128);
    dim3 blk(256);
    size_t sm = GEMM_SMEM_BYTES;
    if (transB) {
        if (hasBias)
            gemm_tf32_kernel<true, true, false><<<grid, blk, sm>>>(A, B, bias, C, M, Ncols);
        else
            gemm_tf32_kernel<true, false, false><<<grid, blk, sm>>>(A, B, bias, C, M, Ncols);
    } else {
        if (hasBias && relu)
            gemm_tf32_kernel<false, true, true><<<grid, blk, sm>>>(A, B, bias, C, M, Ncols);
        else if (hasBias)
            gemm_tf32_kernel<false, true, false><<<grid, blk, sm>>>(A, B, bias, C, M, Ncols);
        else
            gemm_tf32_kernel<false, false, false><<<grid, blk, sm>>>(A, B, bias, C, M, Ncols);
    }
}

extern "C" void kernel_launch(void* const* d_in, const int* in_sizes, int n_in,
                              void* d_out, int out_size) {
    const float* x     = (const float*)d_in[0];
    const int*   ei    = (const int*)  d_in[1];
    const float* ew    = (const float*)d_in[2];
    const float* h0    = (const float*)d_in[3];
    const float* linW  = (const float*)d_in[4];
    const float* linB  = (const float*)d_in[5];
    const float* convW = (const float*)d_in[6];
    const float* convB = (const float*)d_in[7];
    const float* Wih   = (const float*)d_in[8];
    const float* Whh   = (const float*)d_in[9];
    const float* bih   = (const float*)d_in[10];
    const float* bhh   = (const float*)d_in[11];
    const float* fcW   = (const float*)d_in[12];
    const float* fcB   = (const float*)d_in[13];
    float* out = (float*)d_out;

    const int* src = ei;
    const int* dst = ei + EE;

    // one-time: allow >48KB dynamic smem for all tf32 instantiations
    static bool s_attr_done = false;
    if (!s_attr_done) {
        cudaFuncSetAttribute(gemm_tf32_kernel<true, true, false>,
                             cudaFuncAttributeMaxDynamicSharedMemorySize, GEMM_SMEM_BYTES);
        cudaFuncSetAttribute(gemm_tf32_kernel<true, false, false>,
                             cudaFuncAttributeMaxDynamicSharedMemorySize, GEMM_SMEM_BYTES);
        cudaFuncSetAttribute(gemm_tf32_kernel<false, true, true>,
                             cudaFuncAttributeMaxDynamicSharedMemorySize, GEMM_SMEM_BYTES);
        cudaFuncSetAttribute(gemm_tf32_kernel<false, true, false>,
                             cudaFuncAttributeMaxDynamicSharedMemorySize, GEMM_SMEM_BYTES);
        cudaFuncSetAttribute(gemm_tf32_kernel<false, false, false>,
                             cudaFuncAttributeMaxDynamicSharedMemorySize, GEMM_SMEM_BYTES);
        s_attr_done = true;
    }

    // scratch symbol addresses (not stream ops; graph-capture safe)
    float *p_xh, *p_xw, *p_h, *p_gi, *p_gh;
    cudaGetSymbolAddress((void**)&p_xh, g_xh);
    cudaGetSymbolAddress((void**)&p_xw, g_xw);
    cudaGetSymbolAddress((void**)&p_h,  g_h);
    cudaGetSymbolAddress((void**)&p_gi, g_gi);
    cudaGetSymbolAddress((void**)&p_gh, g_gh);

    const size_t NF = (size_t)NN * FH;
    const int EB = 256;

    // degree + normalization
    init_deg_kernel<<<(NN + 255) / 256, 256>>>();
    accum_deg_kernel<<<(EE + EB - 1) / EB, EB>>>(dst, ew);
    dinv_kernel<<<(NN + 255) / 256, 256>>>();

    // xh = relu(x @ linW + linB)
    run_gemm_tf32(x, linW, linB, p_xh, NN, FH, false, true, true);

    // h = GRU(xh, h0)
    run_gemm_tf32(p_xh, Wih, bih, p_gi, NN, H3, true, true, false);
    run_gemm_tf32(h0,   Whh, bhh, p_gh, NN, H3, true, true, false);
    gru_kernel<<<(int)((NF + 255) / 256), 256>>>(p_gi, p_gh, h0, p_h);

    for (int l = 0; l < LL; l++) {
        const float* W = convW + (size_t)l * FH * FH;
        const float* b = convB + (size_t)l * FH;
        // xw = xh @ W
        run_gemm_tf32(p_xh, W, nullptr, p_xw, NN, FH, false, false, false);
        // agg (into xh, overwriting): self-loop + edge scatter
        selfloop_kernel<<<(int)((NF + 255) / 256), 256>>>(p_xw, p_xh);
        scatter_kernel<<<(EE * 32 + 255) / 256, 256>>>(src, dst, ew, p_xw, p_xh);
        // xh = relu(agg + b)
        bias_relu_kernel<<<(int)((NF + 255) / 256), 256>>>(p_xh, b);
        // h = GRU(xh, h)
        run_gemm_tf32(p_xh, Wih, bih, p_gi, NN, H3, true, true, false);
        run_gemm_tf32(p_h,  Whh, bhh, p_gh, NN, H3, true, true, false);
        gru_kernel<<<(int)((NF + 255) / 256), 256>>>(p_gi, p_gh, p_h, p_h);
    }

    // out = h @ fcW + fcB (fp32 fallback: Ncols=40 not a multiple of 128)
    {
        dim3 grid((CC + 63) / 64, (NN + 63) / 64);
        gemm_kernel<false, true, false><<<grid, 256>>>(p_h, fcW, fcB, out, NN, CC);
    }
}